// round 9
// baseline (speedup 1.0000x reference)
#include <cuda_runtime.h>
#include <math.h>

#define BATCH   4096
#define MODES   4
#define LAYERS  4
#define NSTATE  4096
#define NBS     48
#define PACK    344      // sum over N of cnt(N)^2, cnt(N)=8-|N-7|
#define NT      512
#define SSZ     4672     // 4096 + 512 + 64 (swizzled)

__device__ float2 g_Dx[BATCH*MODES*64];
__device__ float2 g_Sq[LAYERS*MODES*64];
__device__ float2 g_Dp[LAYERS*MODES*64];
__device__ float2 g_BS[NBS*PACK];

__constant__ int c_S1[6] = {512,512,512, 64, 64,  8};
__constant__ int c_S2[6] = { 64,  8,  1,  8,  1,  1};
__constant__ int c_T1[6] = {  8, 64, 64,512,512,512};
__constant__ int c_T2[6] = {  1,  1,  8,  1,  8, 64};

__device__ __forceinline__ int SWZ(int i){ return i + (i>>3) + (i>>6); }
__device__ __forceinline__ float2 cmul(float2 a, float2 b){
    return make_float2(a.x*b.x - a.y*b.y, a.x*b.y + a.y*b.x);
}
__device__ __forceinline__ float2 cfma(float2 a, float2 b, float2 c){
    c.x = fmaf(a.x, b.x, fmaf(-a.y, b.y, c.x));
    c.y = fmaf(a.x, b.y, fmaf( a.y, b.x, c.y));
    return c;
}

// ---------- real fp32 8x8 expm ----------
__device__ void matmul8r(const float* A, const float* B, float* C){
    for (int i=0;i<8;i++) for (int j=0;j<8;j++){
        float a = 0.f;
        #pragma unroll
        for (int k=0;k<8;k++) a = fmaf(A[i*8+k], B[k*8+j], a);
        C[i*8+j] = a;
    }
}
__device__ void expm8r(float* X, float* R){
    float fro = 0.f;
    for (int n=0;n<64;n++) fro += X[n]*X[n];
    fro = sqrtf(fro);
    int s = 0;
    while (fro > 0.25f && s < 30){ fro *= 0.5f; s++; }
    float sc = ldexpf(1.f, -s);
    for (int n=0;n<64;n++) X[n] *= sc;
    float T[64];
    for (int n=0;n<64;n++) R[n] = (n%9==0)?1.f:0.f;
    for (int k=10;k>=1;--k){
        matmul8r(X, R, T);
        float inv = 1.f/(float)k;
        for (int n=0;n<64;n++) R[n] = ((n%9==0)?1.f:0.f) + T[n]*inv;
    }
    for (int it=0; it<s; ++it){
        matmul8r(R, R, T);
        for (int n=0;n<64;n++) R[n] = T[n];
    }
}

// ---------- complex fp64 8x8 expm ----------
__device__ void matmul8c(const double2* A, const double2* B, double2* C){
    for (int i=0;i<8;i++) for (int j=0;j<8;j++){
        double2 acc = make_double2(0.0,0.0);
        for (int k=0;k<8;k++){
            double2 a = A[i*8+k], b = B[k*8+j];
            acc.x = fma(a.x,b.x,fma(-a.y,b.y,acc.x));
            acc.y = fma(a.x,b.y,fma( a.y,b.x,acc.y));
        }
        C[i*8+j] = acc;
    }
}
__device__ void expm8c(double2* X, double2* R){
    double fro = 0.0;
    for (int n=0;n<64;n++) fro += X[n].x*X[n].x + X[n].y*X[n].y;
    fro = sqrt(fro);
    int s = 0;
    while (fro > 0.25 && s < 40){ fro *= 0.5; s++; }
    double sc = ldexp(1.0, -s);
    for (int n=0;n<64;n++){ X[n].x *= sc; X[n].y *= sc; }
    double2 T[64];
    for (int n=0;n<64;n++) R[n] = make_double2((n%9==0)?1.0:0.0, 0.0);
    for (int k=12;k>=1;--k){
        matmul8c(X, R, T);
        double inv = 1.0/(double)k;
        for (int n=0;n<64;n++)
            R[n] = make_double2(((n%9==0)?1.0:0.0) + T[n].x*inv, T[n].y*inv);
    }
    for (int it=0; it<s; ++it){
        matmul8c(R, R, T);
        for (int n=0;n<64;n++) R[n] = T[n];
    }
}

// ---------- precompute: per-sample encoding displacements ----------
__global__ void k_dx(const float* __restrict__ x){
    int tid = blockIdx.x*blockDim.x + threadIdx.x;
    if (tid >= BATCH*MODES) return;
    float a = x[tid];
    float X[64], R[64];
    for (int n=0;n<64;n++) X[n] = 0.f;
    for (int n=1;n<8;n++){
        float c = sqrtf((float)n) * a;
        X[n*8+n-1]   =  c;
        X[(n-1)*8+n] = -c;
    }
    expm8r(X, R);
    float2* o = &g_Dx[tid*64];
    for (int n=0;n<64;n++) o[n] = make_float2(R[n], 0.f);
}

// ---------- precompute: BS blocks + squeeze + displacement (fp64) ----------
__global__ void k_gates(const float* __restrict__ th1, const float* __restrict__ ph1,
                        const float* __restrict__ th2, const float* __restrict__ ph2,
                        const float* __restrict__ dr,  const float* __restrict__ dphi,
                        const float* __restrict__ sr,  const float* __restrict__ sphi){
    int tid = blockIdx.x*blockDim.x + threadIdx.x;
    if (tid >= 720 + 32) return;
    double2 X[64], R[64];
    for (int n=0;n<64;n++) X[n] = make_double2(0.0,0.0);

    if (tid < 720){
        int gid = tid/15, N = tid%15;
        int l = gid/12, rem = gid%12, inter = rem/6, p = rem%6;
        const int pi_[6] = {0,0,0,1,1,2};
        const int pj_[6] = {1,2,3,2,3,3};
        int i0 = pi_[p], j0 = pj_[p];
        const float* TH = inter ? th2 : th1;
        const float* PH = inter ? ph2 : ph1;
        double theta = (double)TH[l*16 + i0*4 + j0];
        double phi   = (double)PH[l*16 + i0*4 + j0];
        double post  = (double)PH[l*16 + j0*4 + i0];
        int d = N-7; if (d<0) d = -d;
        int cnt = 8-d;
        int kmin = (N>7) ? (N-7) : 0;
        double cp = cos(phi), sp = sin(phi);
        for (int b=1;b<cnt;b++){               // theta e^{i phi} a1 a2^dag
            int k = kmin+b, lq = N-k;
            double c = sqrt((double)k*(double)(lq+1)) * theta;
            X[(b-1)*8+b] = make_double2(c*cp, c*sp);
        }
        for (int b=0;b<cnt-1;b++){             // -theta e^{-i phi} a1^dag a2
            int k = kmin+b, lq = N-k;
            double c = sqrt((double)(k+1)*(double)lq) * theta;
            X[(b+1)*8+b] = make_double2(-c*cp, c*sp);
        }
        expm8c(X, R);
        for (int a=0;a<cnt;a++){
            int i = kmin+a, j = N-i;
            int r = i*8+j;
            int off = 0;
            for (int rp=0; rp<r; rp++){
                int nn = (rp>>3) + (rp&7);
                int dd = nn-7; if (dd<0) dd = -dd;
                off += 8-dd;
            }
            double pj = post*(double)j;
            double cr = cos(pj), si = sin(pj);
            for (int b=0;b<cnt;b++){
                double2 v = R[a*8+b];
                g_BS[gid*PACK + off + b] =
                    make_float2((float)(cr*v.x - si*v.y), (float)(cr*v.y + si*v.x));
            }
        }
    } else {
        int idx = tid - 720;
        float2* outp;
        if (idx < 16){  // squeeze
            double r = (double)sr[idx], ph = (double)sphi[idx];
            double zx = r*cos(ph), zy = r*sin(ph);
            for (int n=2;n<8;n++){
                double c = 0.5*sqrt((double)(n*(n-1)));
                X[(n-2)*8+n] = make_double2( c*zx, -c*zy);
                X[n*8+(n-2)] = make_double2(-c*zx, -c*zy);
            }
            expm8c(X, R);
            outp = &g_Sq[idx*64];
        } else {        // layer displacement: alpha = (r cos phi) e^{i r sin phi}
            int w = idx-16;
            double r = (double)dr[w], ph = (double)dphi[w];
            double amp = r*cos(ph), an = r*sin(ph);
            double ax = amp*cos(an), ay = amp*sin(an);
            for (int n=1;n<8;n++){
                double c = sqrt((double)n);
                X[n*8+n-1]   = make_double2( c*ax, c*ay);
                X[(n-1)*8+n] = make_double2(-c*ax, c*ay);
            }
            expm8c(X, R);
            outp = &g_Dp[w*64];
        }
        for (int n=0;n<64;n++) outp[n] = make_float2((float)R[n].x, (float)R[n].y);
    }
}

// ---------- main simulation ----------
__device__ __forceinline__ void apply1(float2* st, const float2* U, int sh, int t){
    int S = 1 << sh;
    int low  = t & (S-1);
    int base = ((t >> sh) << (sh+3)) + low;
    float2 s[8];
    #pragma unroll
    for (int j=0;j<8;j++) s[j] = st[SWZ(base + (j<<sh))];
    #pragma unroll
    for (int i=0;i<8;i++){
        float2 a = cmul(U[i*8], s[0]);
        #pragma unroll
        for (int j=1;j<8;j++) a = cfma(U[i*8+j], s[j], a);
        st[SWZ(base + (i<<sh))] = a;
    }
}

__device__ __forceinline__ void apply2(float2* st, const float2* Ug, const int* rof,
                                       int S1, int S2, int T1, int T2, int t){
    int q = t >> 6;
    int g = t & 63;
    int base = (g>>3)*T1 + (g&7)*T2;
    float2 acc[8];
    #pragma unroll
    for (int j=0;j<8;j++){
        int N = q + j;
        int kmin = (N>7) ? (N-7) : 0;
        int cnt  = 8 - ((N>7) ? (N-7) : (7-N));
        const float2* Up = Ug + rof[q*8+j];
        float2 a = make_float2(0.f, 0.f);
        for (int k=0;k<cnt;k++){
            int idx = base + (kmin+k)*S1 + (N-kmin-k)*S2;
            a = cfma(Up[k], st[SWZ(idx)], a);
        }
        acc[j] = a;
    }
    __syncthreads();  // all reads complete before any writes
    #pragma unroll
    for (int j=0;j<8;j++) st[SWZ(base + q*S1 + j*S2)] = acc[j];
}

__global__ __launch_bounds__(NT)
void k_sim(const float* __restrict__ ph1, const float* __restrict__ ph2,
           const float* __restrict__ kerr, float* __restrict__ out){
    __shared__ float2 st[SSZ];
    __shared__ float2 Ug[PACK];
    __shared__ float2 phs[4][8];
    __shared__ int    rof[64];
    __shared__ float  red[16][4];

    int t = threadIdx.x;
    int b = blockIdx.x;

    if (t == 0){
        int off = 0;
        for (int r=0;r<64;r++){
            rof[r] = off;
            int nn = (r>>3) + (r&7);
            int dd = nn-7; if (dd<0) dd = -dd;
            off += 8-dd;
        }
    }
    for (int i=t;i<NSTATE;i+=NT) st[SWZ(i)] = make_float2(0.f,0.f);
    if (t == 0) st[0] = make_float2(1.f,0.f);

    // encoding displacements
    for (int m=0;m<MODES;m++){
        __syncthreads();
        if (t < 64) Ug[t] = g_Dx[(b*4+m)*64 + t];
        __syncthreads();
        apply1(st, Ug, 3*(3-m), t);
    }

    for (int l=0;l<LAYERS;l++){
        for (int half=0; half<2; half++){
            const float* PH = half ? ph2 : ph1;
            // fused diagonal rotations phi[i,i]
            __syncthreads();
            if (t < 32){
                int m = t>>3, n = t&7;
                float sv, cv; sincosf(PH[l*16 + m*5]*(float)n, &sv, &cv);
                phs[m][n] = make_float2(cv, sv);
            }
            __syncthreads();
            for (int i=t;i<NSTATE;i+=NT){
                float2 w = cmul(phs[0][i>>9], phs[1][(i>>6)&7]);
                w = cmul(w, phs[2][(i>>3)&7]);
                w = cmul(w, phs[3][i&7]);
                int p = SWZ(i);
                st[p] = cmul(st[p], w);
            }
            // 6 beamsplitters (post-rotations folded)
            for (int p=0;p<6;p++){
                __syncthreads();
                const float2* src = &g_BS[(l*12 + half*6 + p)*PACK];
                if (t < PACK) Ug[t] = src[t];
                __syncthreads();
                apply2(st, Ug, rof, c_S1[p], c_S2[p], c_T1[p], c_T2[p], t);
            }
            // between interferometers: squeezing; after 2nd: displacement
            const float2* Gset = half ? g_Dp : g_Sq;
            for (int w=0;w<MODES;w++){
                __syncthreads();
                if (t < 64) Ug[t] = Gset[(l*4+w)*64 + t];
                __syncthreads();
                apply1(st, Ug, 3*(3-w), t);
            }
        }
        // Kerr: exp(i kappa n^2)
        __syncthreads();
        if (t < 32){
            int m = t>>3, n = t&7;
            float sv, cv; sincosf(kerr[l*4+m]*(float)(n*n), &sv, &cv);
            phs[m][n] = make_float2(cv, sv);
        }
        __syncthreads();
        for (int i=t;i<NSTATE;i+=NT){
            float2 w = cmul(phs[0][i>>9], phs[1][(i>>6)&7]);
            w = cmul(w, phs[2][(i>>3)&7]);
            w = cmul(w, phs[3][i&7]);
            int p = SWZ(i);
            st[p] = cmul(st[p], w);
        }
    }

    // <n_w> per mode
    __syncthreads();
    float e0=0.f, e1=0.f, e2=0.f, e3=0.f;
    for (int i=t;i<NSTATE;i+=NT){
        float2 v = st[SWZ(i)];
        float p = v.x*v.x + v.y*v.y;
        e0 += p*(float)(i>>9);
        e1 += p*(float)((i>>6)&7);
        e2 += p*(float)((i>>3)&7);
        e3 += p*(float)(i&7);
    }
    #pragma unroll
    for (int o=16;o;o>>=1){
        e0 += __shfl_xor_sync(0xffffffffu, e0, o);
        e1 += __shfl_xor_sync(0xffffffffu, e1, o);
        e2 += __shfl_xor_sync(0xffffffffu, e2, o);
        e3 += __shfl_xor_sync(0xffffffffu, e3, o);
    }
    int wid = t>>5, lane = t&31;
    if (lane == 0){
        red[wid][0]=e0; red[wid][1]=e1; red[wid][2]=e2; red[wid][3]=e3;
    }
    __syncthreads();
    if (t < 4){
        float s = 0.f;
        #pragma unroll
        for (int w=0;w<16;w++) s += red[w][t];
        out[b*4 + t] = s;
    }
}

extern "C" void kernel_launch(void* const* d_in, const int* in_sizes, int n_in,
                              void* d_out, int out_size) {
    const float* x    = (const float*)d_in[0];
    const float* th1  = (const float*)d_in[1];
    const float* ph1  = (const float*)d_in[2];
    const float* th2  = (const float*)d_in[3];
    const float* ph2  = (const float*)d_in[4];
    const float* dr   = (const float*)d_in[5];
    const float* dphi = (const float*)d_in[6];
    const float* sr   = (const float*)d_in[7];
    const float* sphi = (const float*)d_in[8];
    const float* kerr = (const float*)d_in[9];
    float* out = (float*)d_out;

    k_dx<<<(BATCH*MODES + 255)/256, 256>>>(x);
    k_gates<<<3, 256>>>(th1, ph1, th2, ph2, dr, dphi, sr, sphi);
    k_sim<<<BATCH, NT>>>(ph1, ph2, kerr, out);
}

// round 11
// speedup vs baseline: 1.1036x; 1.1036x over previous
#include <cuda_runtime.h>
#include <math.h>

#define BATCH   4096
#define MODES   4
#define LAYERS  4
#define NSTATE  4096
#define NBS     48
#define PACK    344      // sum over N of cnt(N)^2, cnt(N)=8-|N-7|
#define NT      512
#define SSZ     4672     // swizzled extent: max SWZ(4095)=4669

__device__ float2 g_Dx[BATCH*MODES*64];
__device__ float2 g_Sq[LAYERS*MODES*64];
__device__ float2 g_Dp[LAYERS*MODES*64];
__device__ float2 g_BS[NBS*PACK];

// physical (swizzled) strides: logical digit strides (512,64,8,1) -> (584,73,9,1)
__constant__ int c_S1p[6] = {584,584,584, 73, 73,  9};
__constant__ int c_S2p[6] = { 73,  9,  1,  9,  1,  1};
__constant__ int c_T1p[6] = {  9, 73, 73,584,584,584};
__constant__ int c_T2p[6] = {  1,  1,  9,  1,  9, 73};

// packed row offsets: rof[i*8+j] = start of row (i,j) in packed BS matrix
__constant__ int d_rof[64] = {
    0,1,3,6,10,15,21,28,
    36,38,41,45,50,56,63,71,
    78,81,85,90,96,103,111,118,
    124,128,133,139,146,154,161,167,
    172,177,183,190,198,205,211,216,
    220,226,233,241,248,254,259,263,
    266,273,281,288,294,299,303,306,
    308,316,323,329,334,338,341,343};

__device__ __forceinline__ int SWZ(int i){ return i + (i>>3) + (i>>6); }
__device__ __forceinline__ float2 cmul(float2 a, float2 b){
    return make_float2(a.x*b.x - a.y*b.y, a.x*b.y + a.y*b.x);
}
__device__ __forceinline__ float2 cfma(float2 a, float2 b, float2 c){
    c.x = fmaf(a.x, b.x, fmaf(-a.y, b.y, c.x));
    c.y = fmaf(a.x, b.y, fmaf( a.y, b.x, c.y));
    return c;
}

// ---------- real fp32 8x8 expm ----------
__device__ void matmul8r(const float* A, const float* B, float* C){
    for (int i=0;i<8;i++) for (int j=0;j<8;j++){
        float a = 0.f;
        #pragma unroll
        for (int k=0;k<8;k++) a = fmaf(A[i*8+k], B[k*8+j], a);
        C[i*8+j] = a;
    }
}
__device__ void expm8r(float* X, float* R){
    float fro = 0.f;
    for (int n=0;n<64;n++) fro += X[n]*X[n];
    fro = sqrtf(fro);
    int s = 0;
    while (fro > 0.25f && s < 30){ fro *= 0.5f; s++; }
    float sc = ldexpf(1.f, -s);
    for (int n=0;n<64;n++) X[n] *= sc;
    float T[64];
    for (int n=0;n<64;n++) R[n] = (n%9==0)?1.f:0.f;
    for (int k=10;k>=1;--k){
        matmul8r(X, R, T);
        float inv = 1.f/(float)k;
        for (int n=0;n<64;n++) R[n] = ((n%9==0)?1.f:0.f) + T[n]*inv;
    }
    for (int it=0; it<s; ++it){
        matmul8r(R, R, T);
        for (int n=0;n<64;n++) R[n] = T[n];
    }
}

// ---------- complex fp64 8x8 expm ----------
__device__ void matmul8c(const double2* A, const double2* B, double2* C){
    for (int i=0;i<8;i++) for (int j=0;j<8;j++){
        double2 acc = make_double2(0.0,0.0);
        for (int k=0;k<8;k++){
            double2 a = A[i*8+k], b = B[k*8+j];
            acc.x = fma(a.x,b.x,fma(-a.y,b.y,acc.x));
            acc.y = fma(a.x,b.y,fma( a.y,b.x,acc.y));
        }
        C[i*8+j] = acc;
    }
}
__device__ void expm8c(double2* X, double2* R){
    double fro = 0.0;
    for (int n=0;n<64;n++) fro += X[n].x*X[n].x + X[n].y*X[n].y;
    fro = sqrt(fro);
    int s = 0;
    while (fro > 0.25 && s < 40){ fro *= 0.5; s++; }
    double sc = ldexp(1.0, -s);
    for (int n=0;n<64;n++){ X[n].x *= sc; X[n].y *= sc; }
    double2 T[64];
    for (int n=0;n<64;n++) R[n] = make_double2((n%9==0)?1.0:0.0, 0.0);
    for (int k=12;k>=1;--k){
        matmul8c(X, R, T);
        double inv = 1.0/(double)k;
        for (int n=0;n<64;n++)
            R[n] = make_double2(((n%9==0)?1.0:0.0) + T[n].x*inv, T[n].y*inv);
    }
    for (int it=0; it<s; ++it){
        matmul8c(R, R, T);
        for (int n=0;n<64;n++) R[n] = T[n];
    }
}

// ---------- precompute: per-sample encoding displacements ----------
__global__ void k_dx(const float* __restrict__ x){
    int tid = blockIdx.x*blockDim.x + threadIdx.x;
    if (tid >= BATCH*MODES) return;
    float a = x[tid];
    float X[64], R[64];
    for (int n=0;n<64;n++) X[n] = 0.f;
    for (int n=1;n<8;n++){
        float c = sqrtf((float)n) * a;
        X[n*8+n-1]   =  c;
        X[(n-1)*8+n] = -c;
    }
    expm8r(X, R);
    float2* o = &g_Dx[tid*64];
    for (int n=0;n<64;n++) o[n] = make_float2(R[n], 0.f);
}

// ---------- precompute: BS blocks (with diag folding) + squeeze + displacement ----------
__global__ void k_gates(const float* __restrict__ th1, const float* __restrict__ ph1,
                        const float* __restrict__ th2, const float* __restrict__ ph2,
                        const float* __restrict__ dr,  const float* __restrict__ dphi,
                        const float* __restrict__ sr,  const float* __restrict__ sphi,
                        const float* __restrict__ kerr){
    int tid = blockIdx.x*blockDim.x + threadIdx.x;
    if (tid >= 720 + 32) return;
    double2 X[64], R[64];
    for (int n=0;n<64;n++) X[n] = make_double2(0.0,0.0);

    if (tid < 720){
        int gid = tid/15, N = tid%15;
        int l = gid/12, rem = gid%12, inter = rem/6, p = rem%6;
        const int pi_[6] = {0,0,0,1,1,2};
        const int pj_[6] = {1,2,3,2,3,3};
        int i0 = pi_[p], j0 = pj_[p];
        const float* TH = inter ? th2 : th1;
        const float* PH = inter ? ph2 : ph1;
        double theta = (double)TH[l*16 + i0*4 + j0];
        double phi   = (double)PH[l*16 + i0*4 + j0];
        double post  = (double)PH[l*16 + j0*4 + i0];
        // pending diagonal phases to fold on input columns:
        //   p=0 folds modes 0 and 1; p=1 folds mode 2; p=2 folds mode 3.
        //   angle_m(n) = phi[m,m]*n + (inter==0 && l>0 ? kerr[l-1,m]*n^2 : 0)
        double phdA=0.0, kpA=0.0, phdB=0.0, kpB=0.0;
        int foldA = 0, foldB = 0;
        if (p == 0){
            foldA = 1; phdA = (double)PH[l*16 + 0];
            foldB = 1; phdB = (double)PH[l*16 + 5];
            if (inter==0 && l>0){ kpA = (double)kerr[(l-1)*4+0]; kpB = (double)kerr[(l-1)*4+1]; }
        } else if (p == 1){
            foldB = 1; phdB = (double)PH[l*16 + 10];
            if (inter==0 && l>0) kpB = (double)kerr[(l-1)*4+2];
        } else if (p == 2){
            foldB = 1; phdB = (double)PH[l*16 + 15];
            if (inter==0 && l>0) kpB = (double)kerr[(l-1)*4+3];
        }
        int d = N-7; if (d<0) d = -d;
        int cnt = 8-d;
        int kmin = (N>7) ? (N-7) : 0;
        double cp = cos(phi), sp = sin(phi);
        for (int b=1;b<cnt;b++){               // theta e^{i phi} a1 a2^dag
            int k = kmin+b, lq = N-k;
            double c = sqrt((double)k*(double)(lq+1)) * theta;
            X[(b-1)*8+b] = make_double2(c*cp, c*sp);
        }
        for (int b=0;b<cnt-1;b++){             // -theta e^{-i phi} a1^dag a2
            int k = kmin+b, lq = N-k;
            double c = sqrt((double)(k+1)*(double)lq) * theta;
            X[(b+1)*8+b] = make_double2(-c*cp, c*sp);
        }
        expm8c(X, R);
        for (int a=0;a<cnt;a++){
            int i = kmin+a, j = N-i;
            int off = d_rof[i*8+j];
            double pj = post*(double)j;        // folded post-rotation on output mode j0
            for (int b=0;b<cnt;b++){
                int ki = kmin+b, kj = N-ki;    // input photon counts on (i0, j0)
                double ang = pj;
                if (foldA) ang += phdA*(double)ki + kpA*(double)(ki*ki);
                if (foldB) ang += phdB*(double)kj + kpB*(double)(kj*kj);
                double cr = cos(ang), si = sin(ang);
                double2 v = R[a*8+b];
                g_BS[gid*PACK + off + b] =
                    make_float2((float)(cr*v.x - si*v.y), (float)(cr*v.y + si*v.x));
            }
        }
    } else {
        int idx = tid - 720;
        float2* outp;
        if (idx < 16){  // squeeze
            double r = (double)sr[idx], ph = (double)sphi[idx];
            double zx = r*cos(ph), zy = r*sin(ph);
            for (int n=2;n<8;n++){
                double c = 0.5*sqrt((double)(n*(n-1)));
                X[(n-2)*8+n] = make_double2( c*zx, -c*zy);
                X[n*8+(n-2)] = make_double2(-c*zx, -c*zy);
            }
            expm8c(X, R);
            outp = &g_Sq[idx*64];
        } else {        // layer displacement: alpha = (r cos phi) e^{i r sin phi}
            int w = idx-16;
            double r = (double)dr[w], ph = (double)dphi[w];
            double amp = r*cos(ph), an = r*sin(ph);
            double ax = amp*cos(an), ay = amp*sin(an);
            for (int n=1;n<8;n++){
                double c = sqrt((double)n);
                X[n*8+n-1]   = make_double2( c*ax, c*ay);
                X[(n-1)*8+n] = make_double2(-c*ax, c*ay);
            }
            expm8c(X, R);
            outp = &g_Dp[w*64];
        }
        for (int n=0;n<64;n++) outp[n] = make_float2((float)R[n].x, (float)R[n].y);
    }
}

// ---------- main simulation ----------

// single-mode 8x8 gate, mode M compile-time: physical stride + imm-offset LDS/STS
template<int M>
__device__ __forceinline__ void apply1T(float2* st, const float2* U, int t){
    const int Sp = (M==0)?584:(M==1)?73:(M==2)?9:1;
    const int A0 = (M==0)?73:584;
    const int A1 = (M<=1)?9:73;
    const int A2 = (M==3)?9:1;
    int base = (t>>6)*A0 + ((t>>3)&7)*A1 + (t&7)*A2;
    float2 s[8];
    #pragma unroll
    for (int j=0;j<8;j++) s[j] = st[base + j*Sp];
    #pragma unroll
    for (int i=0;i<8;i++){
        float2 a = cmul(U[i*8], s[0]);
        #pragma unroll
        for (int j=1;j<8;j++) a = cfma(U[i*8+j], s[j], a);
        st[base + i*Sp] = a;
    }
}

// BS read phase, q compile-time: fully unrolled exact-count MAC chains
template<int Q>
__device__ __forceinline__ void bs_read(const float2* st, const float2* Ug,
                                        int S1p, int S2p, int base, float2* acc){
    const int dS = S1p - S2p;
    #pragma unroll
    for (int j=0;j<8;j++){
        const int N = Q + j;
        const int kmin = (N>7)?(N-7):0;
        const int cnt  = 8 - ((N>7)?(N-7):(7-N));
        const float2* Up = Ug + d_rof[Q*8+j];
        int idx = base + kmin*S1p + (N-kmin)*S2p;
        float2 a = make_float2(0.f,0.f);
        #pragma unroll
        for (int k=0;k<cnt;k++){ a = cfma(Up[k], st[idx], a); idx += dS; }
        acc[j] = a;
    }
}

__global__ __launch_bounds__(NT)
void k_sim(float* __restrict__ out){
    __shared__ float2 st[SSZ];          // 37376 B
    __shared__ float2 UgA[2][PACK];     // 5504 B  (double-buffered BS gate)
    __shared__ float2 Ug1[4][64];       // 2048 B  (4 single-mode gates)
    __shared__ float  red[16][4];

    int t = threadIdx.x;
    int b = blockIdx.x;

    for (int i=t;i<SSZ;i+=NT) st[i] = make_float2(0.f,0.f);
    if (t == 0) st[0] = make_float2(1.f,0.f);
    for (int i=t;i<256;i+=NT) ((float2*)Ug1)[i] = g_Dx[b*256 + i];
    __syncthreads();

    // encoding displacements
    apply1T<0>(st, Ug1[0], t); __syncthreads();
    apply1T<1>(st, Ug1[1], t); __syncthreads();
    apply1T<2>(st, Ug1[2], t); __syncthreads();
    apply1T<3>(st, Ug1[3], t); __syncthreads();

    for (int hl=0; hl<2*LAYERS; hl++){
        int l = hl>>1, half = hl&1;
        int gi = l*12 + half*6;
        const float2* G1 = half ? &g_Dp[l*256] : &g_Sq[l*256];
        // stage first BS gate + all 4 single-mode gates for this half-layer
        if (t < PACK) UgA[0][t] = g_BS[gi*PACK + t];
        if (t < 256)  ((float2*)Ug1)[t] = G1[t];
        __syncthreads();

        // 6 beamsplitters (pre/post diagonals folded in at precompute)
        for (int p=0;p<6;p++){
            int q = t>>6, g = t&63;               // q warp-uniform
            int S1p = c_S1p[p], S2p = c_S2p[p];
            int base = (g>>3)*c_T1p[p] + (g&7)*c_T2p[p];
            const float2* Ub = UgA[p&1];
            float2 acc[8];
            switch(q){
                case 0: bs_read<0>(st,Ub,S1p,S2p,base,acc); break;
                case 1: bs_read<1>(st,Ub,S1p,S2p,base,acc); break;
                case 2: bs_read<2>(st,Ub,S1p,S2p,base,acc); break;
                case 3: bs_read<3>(st,Ub,S1p,S2p,base,acc); break;
                case 4: bs_read<4>(st,Ub,S1p,S2p,base,acc); break;
                case 5: bs_read<5>(st,Ub,S1p,S2p,base,acc); break;
                case 6: bs_read<6>(st,Ub,S1p,S2p,base,acc); break;
                default: bs_read<7>(st,Ub,S1p,S2p,base,acc); break;
            }
            __syncthreads();                      // uniform: all reads done
            int wb = base + q*S1p;
            #pragma unroll
            for (int j=0;j<8;j++) st[wb + j*S2p] = acc[j];
            if (p < 5 && t < PACK)                // stage next gate in write window
                UgA[(p+1)&1][t] = g_BS[(gi+p+1)*PACK + t];
            __syncthreads();
        }
        // squeeze (half 0) or displacement (half 1)
        apply1T<0>(st, Ug1[0], t); __syncthreads();
        apply1T<1>(st, Ug1[1], t); __syncthreads();
        apply1T<2>(st, Ug1[2], t); __syncthreads();
        apply1T<3>(st, Ug1[3], t); __syncthreads();
    }

    // <n_w> per mode (final Kerr is pure phase: dropped)
    float e0=0.f, e1=0.f, e2=0.f, e3=0.f;
    for (int i=t;i<NSTATE;i+=NT){
        float2 v = st[SWZ(i)];
        float p = v.x*v.x + v.y*v.y;
        e0 += p*(float)(i>>9);
        e1 += p*(float)((i>>6)&7);
        e2 += p*(float)((i>>3)&7);
        e3 += p*(float)(i&7);
    }
    #pragma unroll
    for (int o=16;o;o>>=1){
        e0 += __shfl_xor_sync(0xffffffffu, e0, o);
        e1 += __shfl_xor_sync(0xffffffffu, e1, o);
        e2 += __shfl_xor_sync(0xffffffffu, e2, o);
        e3 += __shfl_xor_sync(0xffffffffu, e3, o);
    }
    int wid = t>>5, lane = t&31;
    if (lane == 0){
        red[wid][0]=e0; red[wid][1]=e1; red[wid][2]=e2; red[wid][3]=e3;
    }
    __syncthreads();
    if (t < 4){
        float s = 0.f;
        #pragma unroll
        for (int w=0;w<16;w++) s += red[w][t];
        out[b*4 + t] = s;
    }
}

extern "C" void kernel_launch(void* const* d_in, const int* in_sizes, int n_in,
                              void* d_out, int out_size) {
    const float* x    = (const float*)d_in[0];
    const float* th1  = (const float*)d_in[1];
    const float* ph1  = (const float*)d_in[2];
    const float* th2  = (const float*)d_in[3];
    const float* ph2  = (const float*)d_in[4];
    const float* dr   = (const float*)d_in[5];
    const float* dphi = (const float*)d_in[6];
    const float* sr   = (const float*)d_in[7];
    const float* sphi = (const float*)d_in[8];
    const float* kerr = (const float*)d_in[9];
    float* out = (float*)d_out;

    k_dx<<<(BATCH*MODES + 255)/256, 256>>>(x);
    k_gates<<<3, 256>>>(th1, ph1, th2, ph2, dr, dphi, sr, sphi, kerr);
    k_sim<<<BATCH, NT>>>(out);
}

// round 14
// speedup vs baseline: 1.1475x; 1.0398x over previous
#include <cuda_runtime.h>
#include <math.h>

#define BATCH   4096
#define MODES   4
#define LAYERS  4
#define NSTATE  4096
#define NBS     48
#define PACK    344
#define NT      512
#define SSZ     4672
#define NGATES  84       // 4 encoding + 8 half-layers * (6 BS + 4 single-mode)

typedef unsigned long long ull;

// gates stored packed for f32x2: (ux, ux, -uy, uy)
__device__ float4 g_Dx4[BATCH*MODES*64];
__device__ float4 g_Sq4[LAYERS*MODES*64];
__device__ float4 g_Dp4[LAYERS*MODES*64];
__device__ float4 g_BS4[NBS*PACK];

// physical (swizzled) strides: logical (512,64,8,1) -> (584,73,9,1)
__constant__ int c_S1p[6] = {584,584,584, 73, 73,  9};
__constant__ int c_S2p[6] = { 73,  9,  1,  9,  1,  1};
__constant__ int c_T1p[6] = {  9, 73, 73,584,584,584};
__constant__ int c_T2p[6] = {  1,  1,  9,  1,  9, 73};
// apply1: remaining-mode base strides + own stride, per mode
__constant__ int c_A0[4] = {73,584,584,584};
__constant__ int c_A1[4] = { 9,  9, 73, 73};
__constant__ int c_A2[4] = { 1,  1,  1,  9};
__constant__ int c_Sp[4] = {584,73,9,1};

__constant__ int d_rof[64] = {
    0,1,3,6,10,15,21,28, 36,38,41,45,50,56,63,71,
    78,81,85,90,96,103,111,118, 124,128,133,139,146,154,161,167,
    172,177,183,190,198,205,211,216, 220,226,233,241,248,254,259,263,
    266,273,281,288,294,299,303,306, 308,316,323,329,334,338,341,343};

__device__ constexpr int ROF[64] = {
    0,1,3,6,10,15,21,28, 36,38,41,45,50,56,63,71,
    78,81,85,90,96,103,111,118, 124,128,133,139,146,154,161,167,
    172,177,183,190,198,205,211,216, 220,226,233,241,248,254,259,263,
    266,273,281,288,294,299,303,306, 308,316,323,329,334,338,341,343};

__device__ __forceinline__ int SWZ(int i){ return i + (i>>3) + (i>>6); }

__device__ __forceinline__ ull pk(float lo, float hi){
    ull r; asm("mov.b64 %0, {%1, %2};" : "=l"(r) : "f"(lo), "f"(hi)); return r;
}
__device__ __forceinline__ float2 upk(ull v){
    float2 r; asm("mov.b64 {%0, %1}, %2;" : "=f"(r.x), "=f"(r.y) : "l"(v)); return r;
}
__device__ __forceinline__ ull f2fma(ull a, ull b, ull c){
    ull d; asm("fma.rn.f32x2 %0, %1, %2, %3;" : "=l"(d) : "l"(a), "l"(b), "l"(c)); return d;
}

// ---------- real fp32 8x8 expm ----------
__device__ void matmul8r(const float* A, const float* B, float* C){
    for (int i=0;i<8;i++) for (int j=0;j<8;j++){
        float a = 0.f;
        #pragma unroll
        for (int k=0;k<8;k++) a = fmaf(A[i*8+k], B[k*8+j], a);
        C[i*8+j] = a;
    }
}
__device__ void expm8r(float* X, float* R){
    float fro = 0.f;
    for (int n=0;n<64;n++) fro += X[n]*X[n];
    fro = sqrtf(fro);
    int s = 0;
    while (fro > 0.25f && s < 30){ fro *= 0.5f; s++; }
    float sc = ldexpf(1.f, -s);
    for (int n=0;n<64;n++) X[n] *= sc;
    float T[64];
    for (int n=0;n<64;n++) R[n] = (n%9==0)?1.f:0.f;
    for (int k=10;k>=1;--k){
        matmul8r(X, R, T);
        float inv = 1.f/(float)k;
        for (int n=0;n<64;n++) R[n] = ((n%9==0)?1.f:0.f) + T[n]*inv;
    }
    for (int it=0; it<s; ++it){
        matmul8r(R, R, T);
        for (int n=0;n<64;n++) R[n] = T[n];
    }
}

// ---------- complex fp64 8x8 expm ----------
__device__ void matmul8c(const double2* A, const double2* B, double2* C){
    for (int i=0;i<8;i++) for (int j=0;j<8;j++){
        double2 acc = make_double2(0.0,0.0);
        for (int k=0;k<8;k++){
            double2 a = A[i*8+k], b = B[k*8+j];
            acc.x = fma(a.x,b.x,fma(-a.y,b.y,acc.x));
            acc.y = fma(a.x,b.y,fma( a.y,b.x,acc.y));
        }
        C[i*8+j] = acc;
    }
}
__device__ void expm8c(double2* X, double2* R){
    double fro = 0.0;
    for (int n=0;n<64;n++) fro += X[n].x*X[n].x + X[n].y*X[n].y;
    fro = sqrt(fro);
    int s = 0;
    while (fro > 0.25 && s < 40){ fro *= 0.5; s++; }
    double sc = ldexp(1.0, -s);
    for (int n=0;n<64;n++){ X[n].x *= sc; X[n].y *= sc; }
    double2 T[64];
    for (int n=0;n<64;n++) R[n] = make_double2((n%9==0)?1.0:0.0, 0.0);
    for (int k=12;k>=1;--k){
        matmul8c(X, R, T);
        double inv = 1.0/(double)k;
        for (int n=0;n<64;n++)
            R[n] = make_double2(((n%9==0)?1.0:0.0) + T[n].x*inv, T[n].y*inv);
    }
    for (int it=0; it<s; ++it){
        matmul8c(R, R, T);
        for (int n=0;n<64;n++) R[n] = T[n];
    }
}

// ---------- precompute: per-sample encoding displacements ----------
__global__ void k_dx(const float* __restrict__ x){
    int tid = blockIdx.x*blockDim.x + threadIdx.x;
    if (tid >= BATCH*MODES) return;
    float a = x[tid];
    float X[64], R[64];
    for (int n=0;n<64;n++) X[n] = 0.f;
    for (int n=1;n<8;n++){
        float c = sqrtf((float)n) * a;
        X[n*8+n-1]   =  c;
        X[(n-1)*8+n] = -c;
    }
    expm8r(X, R);
    float4* o = &g_Dx4[tid*64];
    for (int n=0;n<64;n++) o[n] = make_float4(R[n], R[n], 0.f, 0.f);
}

// ---------- precompute: BS blocks (diag folding) + squeeze + displacement ----------
__global__ void k_gates(const float* __restrict__ th1, const float* __restrict__ ph1,
                        const float* __restrict__ th2, const float* __restrict__ ph2,
                        const float* __restrict__ dr,  const float* __restrict__ dphi,
                        const float* __restrict__ sr,  const float* __restrict__ sphi,
                        const float* __restrict__ kerr){
    int tid = blockIdx.x*blockDim.x + threadIdx.x;
    if (tid >= 720 + 32) return;
    double2 X[64], R[64];
    for (int n=0;n<64;n++) X[n] = make_double2(0.0,0.0);

    if (tid < 720){
        int gid = tid/15, N = tid%15;
        int l = gid/12, rem = gid%12, inter = rem/6, p = rem%6;
        const int pi_[6] = {0,0,0,1,1,2};
        const int pj_[6] = {1,2,3,2,3,3};
        int i0 = pi_[p], j0 = pj_[p];
        const float* TH = inter ? th2 : th1;
        const float* PH = inter ? ph2 : ph1;
        double theta = (double)TH[l*16 + i0*4 + j0];
        double phi   = (double)PH[l*16 + i0*4 + j0];
        double post  = (double)PH[l*16 + j0*4 + i0];
        double phdA=0.0, kpA=0.0, phdB=0.0, kpB=0.0;
        int foldA = 0, foldB = 0;
        if (p == 0){
            foldA = 1; phdA = (double)PH[l*16 + 0];
            foldB = 1; phdB = (double)PH[l*16 + 5];
            if (inter==0 && l>0){ kpA = (double)kerr[(l-1)*4+0]; kpB = (double)kerr[(l-1)*4+1]; }
        } else if (p == 1){
            foldB = 1; phdB = (double)PH[l*16 + 10];
            if (inter==0 && l>0) kpB = (double)kerr[(l-1)*4+2];
        } else if (p == 2){
            foldB = 1; phdB = (double)PH[l*16 + 15];
            if (inter==0 && l>0) kpB = (double)kerr[(l-1)*4+3];
        }
        int d = N-7; if (d<0) d = -d;
        int cnt = 8-d;
        int kmin = (N>7) ? (N-7) : 0;
        double cp = cos(phi), sp = sin(phi);
        for (int b=1;b<cnt;b++){
            int k = kmin+b, lq = N-k;
            double c = sqrt((double)k*(double)(lq+1)) * theta;
            X[(b-1)*8+b] = make_double2(c*cp, c*sp);
        }
        for (int b=0;b<cnt-1;b++){
            int k = kmin+b, lq = N-k;
            double c = sqrt((double)(k+1)*(double)lq) * theta;
            X[(b+1)*8+b] = make_double2(-c*cp, c*sp);
        }
        expm8c(X, R);
        for (int a=0;a<cnt;a++){
            int i = kmin+a, j = N-i;
            int off = d_rof[i*8+j];
            double pj = post*(double)j;
            for (int b=0;b<cnt;b++){
                int ki = kmin+b, kj = N-ki;
                double ang = pj;
                if (foldA) ang += phdA*(double)ki + kpA*(double)(ki*ki);
                if (foldB) ang += phdB*(double)kj + kpB*(double)(kj*kj);
                double cr = cos(ang), si = sin(ang);
                double2 v = R[a*8+b];
                float ux = (float)(cr*v.x - si*v.y);
                float uy = (float)(cr*v.y + si*v.x);
                g_BS4[gid*PACK + off + b] = make_float4(ux, ux, -uy, uy);
            }
        }
    } else {
        int idx = tid - 720;
        float4* outp;
        if (idx < 16){
            double r = (double)sr[idx], ph = (double)sphi[idx];
            double zx = r*cos(ph), zy = r*sin(ph);
            for (int n=2;n<8;n++){
                double c = 0.5*sqrt((double)(n*(n-1)));
                X[(n-2)*8+n] = make_double2( c*zx, -c*zy);
                X[n*8+(n-2)] = make_double2(-c*zx, -c*zy);
            }
            expm8c(X, R);
            outp = &g_Sq4[idx*64];
        } else {
            int w = idx-16;
            double r = (double)dr[w], ph = (double)dphi[w];
            double amp = r*cos(ph), an = r*sin(ph);
            double ax = amp*cos(an), ay = amp*sin(an);
            for (int n=1;n<8;n++){
                double c = sqrt((double)n);
                X[n*8+n-1]   = make_double2( c*ax, c*ay);
                X[(n-1)*8+n] = make_double2(-c*ax, c*ay);
            }
            expm8c(X, R);
            outp = &g_Dp4[w*64];
        }
        for (int n=0;n<64;n++)
            outp[n] = make_float4((float)R[n].x, (float)R[n].x, -(float)R[n].y, (float)R[n].y);
    }
}

// ---------- main simulation ----------

// closed N-diagonal matvec: load cnt inputs once, cnt^2 packed cMACs, store cnt outputs
template<int N>
__device__ __forceinline__ void bs_diag(float2* st, const float4* Ub,
                                        int base, int S1p, int S2p){
    constexpr int kmin = (N>7)?(N-7):0;
    constexpr int cnt  = 8 - ((N>7)?(N-7):(7-N));
    const int dS = S1p - S2p;
    const int a0 = base + kmin*S1p + (N-kmin)*S2p;
    ull acc[cnt];
    #pragma unroll
    for (int a=0;a<cnt;a++) acc[a] = 0ull;
    int addr = a0;
    #pragma unroll
    for (int b=0;b<cnt;b++){
        float2 s = st[addr];
        ull S  = pk(s.x, s.y);
        ull SW = pk(s.y, s.x);
        #pragma unroll
        for (int a=0;a<cnt;a++){
            ulonglong2 u = *reinterpret_cast<const ulonglong2*>(
                &Ub[ROF[(kmin+a)*8 + (N-kmin-a)] + b]);
            acc[a] = f2fma(u.x, S,  acc[a]);
            acc[a] = f2fma(u.y, SW, acc[a]);
        }
        addr += dS;
    }
    addr = a0;
    #pragma unroll
    for (int a=0;a<cnt;a++){ st[addr] = upk(acc[a]); addr += dS; }
}

template<int QQ>
__device__ __forceinline__ void bs_bucket(float2* st, const float4* Ub,
                                          int base, int S1p, int S2p){
    if constexpr (QQ==0){ bs_diag<7>(st,Ub,base,S1p,S2p); }
    if constexpr (QQ==1){ bs_diag<6>(st,Ub,base,S1p,S2p); }
    if constexpr (QQ==2){ bs_diag<8>(st,Ub,base,S1p,S2p); }
    if constexpr (QQ==3){ bs_diag<5>(st,Ub,base,S1p,S2p); bs_diag<0>(st,Ub,base,S1p,S2p); }
    if constexpr (QQ==4){ bs_diag<9>(st,Ub,base,S1p,S2p); bs_diag<14>(st,Ub,base,S1p,S2p); }
    if constexpr (QQ==5){ bs_diag<4>(st,Ub,base,S1p,S2p); bs_diag<13>(st,Ub,base,S1p,S2p); }
    if constexpr (QQ==6){ bs_diag<10>(st,Ub,base,S1p,S2p); bs_diag<1>(st,Ub,base,S1p,S2p); }
    if constexpr (QQ==7){ bs_diag<3>(st,Ub,base,S1p,S2p); bs_diag<11>(st,Ub,base,S1p,S2p);
                          bs_diag<2>(st,Ub,base,S1p,S2p); bs_diag<12>(st,Ub,base,S1p,S2p); }
}

// single-mode 8x8 gate, closed per-thread row, packed math
__device__ __forceinline__ void apply1p(float2* st, const float4* Ub, int base, int Sp){
    ull acc[8];
    #pragma unroll
    for (int i=0;i<8;i++) acc[i] = 0ull;
    int addr = base;
    #pragma unroll
    for (int j=0;j<8;j++){
        float2 s = st[addr];
        ull S  = pk(s.x, s.y);
        ull SW = pk(s.y, s.x);
        #pragma unroll
        for (int i=0;i<8;i++){
            ulonglong2 u = *reinterpret_cast<const ulonglong2*>(&Ub[i*8+j]);
            acc[i] = f2fma(u.x, S,  acc[i]);
            acc[i] = f2fma(u.y, SW, acc[i]);
        }
        addr += Sp;
    }
    addr = base;
    #pragma unroll
    for (int i=0;i<8;i++){ st[addr] = upk(acc[i]); addr += Sp; }
}

// gate descriptor: kind 0..3 = apply1 mode; 4+p = BS pair p
struct GateRef { const float4* src; int n; int kind; };
__device__ __forceinline__ GateRef gate_ref(int s, int b){
    GateRef g;
    if (s < 4){ g.src = g_Dx4 + (b*4+s)*64; g.n = 64; g.kind = s; return g; }
    int u = s-4, hl = u/10, r = u%10, l = hl>>1, half = hl&1;
    if (r < 6){ g.src = g_BS4 + (l*12+half*6+r)*PACK; g.n = PACK; g.kind = 4+r; return g; }
    int m = r-6;
    g.src = (half ? g_Dp4 : g_Sq4) + (l*4+m)*64; g.n = 64; g.kind = m; return g;
}

__global__ __launch_bounds__(NT, 2)
void k_sim(float* __restrict__ out){
    __shared__ float2 st[SSZ];          // 37376 B
    __shared__ float4 buf[2][PACK];     // 11008 B  (ping-pong gate buffer)
    __shared__ float  red[16][4];

    int t = threadIdx.x;
    int b = blockIdx.x;
    int qq = t >> 6, g = t & 63;

    for (int i=t;i<SSZ;i+=NT) st[i] = make_float2(0.f,0.f);
    if (t == 0) st[0] = make_float2(1.f,0.f);
    {   // stage gate 0
        GateRef g0 = gate_ref(0, b);
        if (t < g0.n) buf[0][t] = __ldg(&g0.src[t]);
    }
    __syncthreads();

    for (int s=0; s<NGATES; s++){
        // prefetch next gate (LDG latency hidden under compute)
        float4 pre; int pn = 0;
        if (s+1 < NGATES){
            GateRef gn = gate_ref(s+1, b);
            pn = gn.n;
            if (t < pn) pre = __ldg(&gn.src[t]);
        }
        GateRef gc = gate_ref(s, b);
        const float4* Ub = buf[s&1];
        if (gc.kind < 4){
            int m = gc.kind;
            int base = (t>>6)*c_A0[m] + ((t>>3)&7)*c_A1[m] + (t&7)*c_A2[m];
            apply1p(st, Ub, base, c_Sp[m]);
        } else {
            int p = gc.kind - 4;
            int S1p = c_S1p[p], S2p = c_S2p[p];
            int base = (g>>3)*c_T1p[p] + (g&7)*c_T2p[p];
            switch(qq){
                case 0: bs_bucket<0>(st,Ub,base,S1p,S2p); break;
                case 1: bs_bucket<1>(st,Ub,base,S1p,S2p); break;
                case 2: bs_bucket<2>(st,Ub,base,S1p,S2p); break;
                case 3: bs_bucket<3>(st,Ub,base,S1p,S2p); break;
                case 4: bs_bucket<4>(st,Ub,base,S1p,S2p); break;
                case 5: bs_bucket<5>(st,Ub,base,S1p,S2p); break;
                case 6: bs_bucket<6>(st,Ub,base,S1p,S2p); break;
                default: bs_bucket<7>(st,Ub,base,S1p,S2p); break;
            }
        }
        if (t < pn) buf[(s+1)&1][t] = pre;
        __syncthreads();
    }

    // <n_w> per mode (final Kerr is pure phase: dropped)
    float e0=0.f, e1=0.f, e2=0.f, e3=0.f;
    for (int i=t;i<NSTATE;i+=NT){
        float2 v = st[SWZ(i)];
        float p = v.x*v.x + v.y*v.y;
        e0 += p*(float)(i>>9);
        e1 += p*(float)((i>>6)&7);
        e2 += p*(float)((i>>3)&7);
        e3 += p*(float)(i&7);
    }
    #pragma unroll
    for (int o=16;o;o>>=1){
        e0 += __shfl_xor_sync(0xffffffffu, e0, o);
        e1 += __shfl_xor_sync(0xffffffffu, e1, o);
        e2 += __shfl_xor_sync(0xffffffffu, e2, o);
        e3 += __shfl_xor_sync(0xffffffffu, e3, o);
    }
    int wid = t>>5, lane = t&31;
    if (lane == 0){
        red[wid][0]=e0; red[wid][1]=e1; red[wid][2]=e2; red[wid][3]=e3;
    }
    __syncthreads();
    if (t < 4){
        float sm = 0.f;
        #pragma unroll
        for (int w=0;w<16;w++) sm += red[w][t];
        out[b*4 + t] = sm;
    }
}

extern "C" void kernel_launch(void* const* d_in, const int* in_sizes, int n_in,
                              void* d_out, int out_size) {
    const float* x    = (const float*)d_in[0];
    const float* th1  = (const float*)d_in[1];
    const float* ph1  = (const float*)d_in[2];
    const float* th2  = (const float*)d_in[3];
    const float* ph2  = (const float*)d_in[4];
    const float* dr   = (const float*)d_in[5];
    const float* dphi = (const float*)d_in[6];
    const float* sr   = (const float*)d_in[7];
    const float* sphi = (const float*)d_in[8];
    const float* kerr = (const float*)d_in[9];
    float* out = (float*)d_out;

    k_dx<<<(BATCH*MODES + 255)/256, 256>>>(x);
    k_gates<<<3, 256>>>(th1, ph1, th2, ph2, dr, dphi, sr, sphi, kerr);
    k_sim<<<BATCH, NT>>>(out);
}

// round 15
// speedup vs baseline: 1.2927x; 1.1266x over previous
#include <cuda_runtime.h>
#include <math.h>

#define BATCH   4096
#define MODES   4
#define LAYERS  4
#define NSTATE  4096
#define NBS     48
#define PACK    344
#define NT      512
#define SSZ     4672          // swizzled extent: max SWZ(4095)=4669
#define NGATES  84            // 4 encoding + 8 half-layers * (6 BS + 4 single-mode)
#define SMEM_BYTES (2*SSZ*8 + 2*PACK*8 + 64*4)   // 74752 + 5504 + 256 = 80512

typedef unsigned long long ull;

// gates stored as plain complex float2 (ux, uy)
__device__ float2 g_Dx2[BATCH*MODES*64];
__device__ float2 g_Sq2[LAYERS*MODES*64];
__device__ float2 g_Dp2[LAYERS*MODES*64];
__device__ float2 g_BS2[NBS*PACK];

// physical (swizzled) strides: logical (512,64,8,1) -> (584,73,9,1)
__constant__ int c_S1p[6] = {584,584,584, 73, 73,  9};
__constant__ int c_S2p[6] = { 73,  9,  1,  9,  1,  1};
__constant__ int c_T1p[6] = {  9, 73, 73,584,584,584};
__constant__ int c_T2p[6] = {  1,  1,  9,  1,  9, 73};
__constant__ int c_A0[4] = {73,584,584,584};
__constant__ int c_A1[4] = { 9,  9, 73, 73};
__constant__ int c_A2[4] = { 1,  1,  1,  9};
__constant__ int c_Sp[4] = {584,73,9,1};

__constant__ int d_rof[64] = {
    0,1,3,6,10,15,21,28, 36,38,41,45,50,56,63,71,
    78,81,85,90,96,103,111,118, 124,128,133,139,146,154,161,167,
    172,177,183,190,198,205,211,216, 220,226,233,241,248,254,259,263,
    266,273,281,288,294,299,303,306, 308,316,323,329,334,338,341,343};

__device__ constexpr int ROF[64] = {
    0,1,3,6,10,15,21,28, 36,38,41,45,50,56,63,71,
    78,81,85,90,96,103,111,118, 124,128,133,139,146,154,161,167,
    172,177,183,190,198,205,211,216, 220,226,233,241,248,254,259,263,
    266,273,281,288,294,299,303,306, 308,316,323,329,334,338,341,343};

__device__ __forceinline__ int SWZ(int i){ return i + (i>>3) + (i>>6); }

__device__ __forceinline__ ull pk(float lo, float hi){
    ull r; asm("mov.b64 %0, {%1, %2};" : "=l"(r) : "f"(lo), "f"(hi)); return r;
}
__device__ __forceinline__ float2 upk(ull v){
    float2 r; asm("mov.b64 {%0, %1}, %2;" : "=f"(r.x), "=f"(r.y) : "l"(v)); return r;
}
__device__ __forceinline__ ull f2fma(ull a, ull b, ull c){
    ull d; asm("fma.rn.f32x2 %0, %1, %2, %3;" : "=l"(d) : "l"(a), "l"(b), "l"(c)); return d;
}

// ---------- real fp32 8x8 expm ----------
__device__ void matmul8r(const float* A, const float* B, float* C){
    for (int i=0;i<8;i++) for (int j=0;j<8;j++){
        float a = 0.f;
        #pragma unroll
        for (int k=0;k<8;k++) a = fmaf(A[i*8+k], B[k*8+j], a);
        C[i*8+j] = a;
    }
}
__device__ void expm8r(float* X, float* R){
    float fro = 0.f;
    for (int n=0;n<64;n++) fro += X[n]*X[n];
    fro = sqrtf(fro);
    int s = 0;
    while (fro > 0.25f && s < 30){ fro *= 0.5f; s++; }
    float sc = ldexpf(1.f, -s);
    for (int n=0;n<64;n++) X[n] *= sc;
    float T[64];
    for (int n=0;n<64;n++) R[n] = (n%9==0)?1.f:0.f;
    for (int k=10;k>=1;--k){
        matmul8r(X, R, T);
        float inv = 1.f/(float)k;
        for (int n=0;n<64;n++) R[n] = ((n%9==0)?1.f:0.f) + T[n]*inv;
    }
    for (int it=0; it<s; ++it){
        matmul8r(R, R, T);
        for (int n=0;n<64;n++) R[n] = T[n];
    }
}

// ---------- complex fp64 8x8 expm ----------
__device__ void matmul8c(const double2* A, const double2* B, double2* C){
    for (int i=0;i<8;i++) for (int j=0;j<8;j++){
        double2 acc = make_double2(0.0,0.0);
        for (int k=0;k<8;k++){
            double2 a = A[i*8+k], b = B[k*8+j];
            acc.x = fma(a.x,b.x,fma(-a.y,b.y,acc.x));
            acc.y = fma(a.x,b.y,fma( a.y,b.x,acc.y));
        }
        C[i*8+j] = acc;
    }
}
__device__ void expm8c(double2* X, double2* R){
    double fro = 0.0;
    for (int n=0;n<64;n++) fro += X[n].x*X[n].x + X[n].y*X[n].y;
    fro = sqrt(fro);
    int s = 0;
    while (fro > 0.25 && s < 40){ fro *= 0.5; s++; }
    double sc = ldexp(1.0, -s);
    for (int n=0;n<64;n++){ X[n].x *= sc; X[n].y *= sc; }
    double2 T[64];
    for (int n=0;n<64;n++) R[n] = make_double2((n%9==0)?1.0:0.0, 0.0);
    for (int k=12;k>=1;--k){
        matmul8c(X, R, T);
        double inv = 1.0/(double)k;
        for (int n=0;n<64;n++)
            R[n] = make_double2(((n%9==0)?1.0:0.0) + T[n].x*inv, T[n].y*inv);
    }
    for (int it=0; it<s; ++it){
        matmul8c(R, R, T);
        for (int n=0;n<64;n++) R[n] = T[n];
    }
}

// ---------- merged precompute: blocks 0..63 = encoding dx, blocks 64..66 = shared gates ----------
__global__ void k_prep(const float* __restrict__ x,
                       const float* __restrict__ th1, const float* __restrict__ ph1,
                       const float* __restrict__ th2, const float* __restrict__ ph2,
                       const float* __restrict__ dr,  const float* __restrict__ dphi,
                       const float* __restrict__ sr,  const float* __restrict__ sphi,
                       const float* __restrict__ kerr){
    int bid = blockIdx.x, t = threadIdx.x;
    if (bid < 64){
        int tid = bid*256 + t;      // 0..16383: per-sample encoding displacement
        float a = x[tid];
        float X[64], R[64];
        for (int n=0;n<64;n++) X[n] = 0.f;
        for (int n=1;n<8;n++){
            float c = sqrtf((float)n) * a;
            X[n*8+n-1]   =  c;
            X[(n-1)*8+n] = -c;
        }
        expm8r(X, R);
        float2* o = &g_Dx2[tid*64];
        for (int n=0;n<64;n++) o[n] = make_float2(R[n], 0.f);
        return;
    }
    int tid = (bid-64)*256 + t;
    if (tid >= 720 + 32) return;
    double2 X[64], R[64];
    for (int n=0;n<64;n++) X[n] = make_double2(0.0,0.0);

    if (tid < 720){
        int gid = tid/15, N = tid%15;
        int l = gid/12, rem = gid%12, inter = rem/6, p = rem%6;
        const int pi_[6] = {0,0,0,1,1,2};
        const int pj_[6] = {1,2,3,2,3,3};
        int i0 = pi_[p], j0 = pj_[p];
        const float* TH = inter ? th2 : th1;
        const float* PH = inter ? ph2 : ph1;
        double theta = (double)TH[l*16 + i0*4 + j0];
        double phi   = (double)PH[l*16 + i0*4 + j0];
        double post  = (double)PH[l*16 + j0*4 + i0];
        double phdA=0.0, kpA=0.0, phdB=0.0, kpB=0.0;
        int foldA = 0, foldB = 0;
        if (p == 0){
            foldA = 1; phdA = (double)PH[l*16 + 0];
            foldB = 1; phdB = (double)PH[l*16 + 5];
            if (inter==0 && l>0){ kpA = (double)kerr[(l-1)*4+0]; kpB = (double)kerr[(l-1)*4+1]; }
        } else if (p == 1){
            foldB = 1; phdB = (double)PH[l*16 + 10];
            if (inter==0 && l>0) kpB = (double)kerr[(l-1)*4+2];
        } else if (p == 2){
            foldB = 1; phdB = (double)PH[l*16 + 15];
            if (inter==0 && l>0) kpB = (double)kerr[(l-1)*4+3];
        }
        int d = N-7; if (d<0) d = -d;
        int cnt = 8-d;
        int kmin = (N>7) ? (N-7) : 0;
        double cp = cos(phi), sp = sin(phi);
        for (int b=1;b<cnt;b++){
            int k = kmin+b, lq = N-k;
            double c = sqrt((double)k*(double)(lq+1)) * theta;
            X[(b-1)*8+b] = make_double2(c*cp, c*sp);
        }
        for (int b=0;b<cnt-1;b++){
            int k = kmin+b, lq = N-k;
            double c = sqrt((double)(k+1)*(double)lq) * theta;
            X[(b+1)*8+b] = make_double2(-c*cp, c*sp);
        }
        expm8c(X, R);
        for (int a=0;a<cnt;a++){
            int i = kmin+a, j = N-i;
            int off = d_rof[i*8+j];
            double pj = post*(double)j;
            for (int b=0;b<cnt;b++){
                int ki = kmin+b, kj = N-ki;
                double ang = pj;
                if (foldA) ang += phdA*(double)ki + kpA*(double)(ki*ki);
                if (foldB) ang += phdB*(double)kj + kpB*(double)(kj*kj);
                double cr = cos(ang), si = sin(ang);
                double2 v = R[a*8+b];
                g_BS2[gid*PACK + off + b] =
                    make_float2((float)(cr*v.x - si*v.y), (float)(cr*v.y + si*v.x));
            }
        }
    } else {
        int idx = tid - 720;
        float2* outp;
        if (idx < 16){
            double r = (double)sr[idx], ph = (double)sphi[idx];
            double zx = r*cos(ph), zy = r*sin(ph);
            for (int n=2;n<8;n++){
                double c = 0.5*sqrt((double)(n*(n-1)));
                X[(n-2)*8+n] = make_double2( c*zx, -c*zy);
                X[n*8+(n-2)] = make_double2(-c*zx, -c*zy);
            }
            expm8c(X, R);
            outp = &g_Sq2[idx*64];
        } else {
            int w = idx-16;
            double r = (double)dr[w], ph = (double)dphi[w];
            double amp = r*cos(ph), an = r*sin(ph);
            double ax = amp*cos(an), ay = amp*sin(an);
            for (int n=1;n<8;n++){
                double c = sqrt((double)n);
                X[n*8+n-1]   = make_double2( c*ax, c*ay);
                X[(n-1)*8+n] = make_double2(-c*ax, c*ay);
            }
            expm8c(X, R);
            outp = &g_Dp2[w*64];
        }
        for (int n=0;n<64;n++) outp[n] = make_float2((float)R[n].x, (float)R[n].y);
    }
}

// ---------- main simulation: 2 samples per CTA ----------

// closed N-diagonal matvec on two states, gate shared (or split for encoding)
template<int N, bool SPLIT>
__device__ __forceinline__ void bs_diag2(float2* st0, float2* st1,
                                         const float2* U0, const float2* U1,
                                         int base, int S1p, int S2p){
    constexpr int kmin = (N>7)?(N-7):0;
    constexpr int cnt  = 8 - ((N>7)?(N-7):(7-N));
    const int dS = S1p - S2p;
    const int a0 = base + kmin*S1p + (N-kmin)*S2p;
    ull acc0[cnt], acc1[cnt];
    #pragma unroll
    for (int a=0;a<cnt;a++){ acc0[a]=0ull; acc1[a]=0ull; }
    int addr = a0;
    #pragma unroll
    for (int b=0;b<cnt;b++){
        float2 s0 = st0[addr], s1 = st1[addr];
        ull A0_ = pk(s0.x, s0.y), W0 = pk(-s0.y, s0.x);
        ull A1_ = pk(s1.x, s1.y), W1 = pk(-s1.y, s1.x);
        #pragma unroll
        for (int a=0;a<cnt;a++){
            int ui = ROF[(kmin+a)*8 + (N-kmin-a)] + b;
            float2 u = U0[ui];
            ull UX = pk(u.x,u.x), UY = pk(u.y,u.y);
            acc0[a] = f2fma(UX, A0_, acc0[a]);
            acc0[a] = f2fma(UY, W0,  acc0[a]);
            if (SPLIT){ float2 v = U1[ui]; UX = pk(v.x,v.x); UY = pk(v.y,v.y); }
            acc1[a] = f2fma(UX, A1_, acc1[a]);
            acc1[a] = f2fma(UY, W1,  acc1[a]);
        }
        addr += dS;
    }
    addr = a0;
    #pragma unroll
    for (int a=0;a<cnt;a++){ st0[addr]=upk(acc0[a]); st1[addr]=upk(acc1[a]); addr += dS; }
}

template<int QQ>
__device__ __forceinline__ void bs_bucket2(float2* st0, float2* st1, const float2* Ub,
                                           int base, int S1p, int S2p){
    if constexpr (QQ==0){ bs_diag2<7,false>(st0,st1,Ub,Ub,base,S1p,S2p); }
    if constexpr (QQ==1){ bs_diag2<6,false>(st0,st1,Ub,Ub,base,S1p,S2p); }
    if constexpr (QQ==2){ bs_diag2<8,false>(st0,st1,Ub,Ub,base,S1p,S2p); }
    if constexpr (QQ==3){ bs_diag2<5,false>(st0,st1,Ub,Ub,base,S1p,S2p);
                          bs_diag2<0,false>(st0,st1,Ub,Ub,base,S1p,S2p); }
    if constexpr (QQ==4){ bs_diag2<9,false>(st0,st1,Ub,Ub,base,S1p,S2p);
                          bs_diag2<14,false>(st0,st1,Ub,Ub,base,S1p,S2p); }
    if constexpr (QQ==5){ bs_diag2<4,false>(st0,st1,Ub,Ub,base,S1p,S2p);
                          bs_diag2<13,false>(st0,st1,Ub,Ub,base,S1p,S2p); }
    if constexpr (QQ==6){ bs_diag2<10,false>(st0,st1,Ub,Ub,base,S1p,S2p);
                          bs_diag2<1,false>(st0,st1,Ub,Ub,base,S1p,S2p); }
    if constexpr (QQ==7){ bs_diag2<3,false>(st0,st1,Ub,Ub,base,S1p,S2p);
                          bs_diag2<11,false>(st0,st1,Ub,Ub,base,S1p,S2p);
                          bs_diag2<2,false>(st0,st1,Ub,Ub,base,S1p,S2p);
                          bs_diag2<12,false>(st0,st1,Ub,Ub,base,S1p,S2p); }
}

// single-mode 8x8 gate on two states
template<bool SPLIT>
__device__ __forceinline__ void apply1p2(float2* st0, float2* st1,
                                         const float2* U0, const float2* U1,
                                         int base, int Sp){
    ull acc0[8], acc1[8];
    #pragma unroll
    for (int i=0;i<8;i++){ acc0[i]=0ull; acc1[i]=0ull; }
    int addr = base;
    #pragma unroll
    for (int j=0;j<8;j++){
        float2 s0 = st0[addr], s1 = st1[addr];
        ull A0_ = pk(s0.x, s0.y), W0 = pk(-s0.y, s0.x);
        ull A1_ = pk(s1.x, s1.y), W1 = pk(-s1.y, s1.x);
        #pragma unroll
        for (int i=0;i<8;i++){
            float2 u = U0[i*8+j];
            ull UX = pk(u.x,u.x), UY = pk(u.y,u.y);
            acc0[i] = f2fma(UX, A0_, acc0[i]);
            acc0[i] = f2fma(UY, W0,  acc0[i]);
            if (SPLIT){ float2 v = U1[i*8+j]; UX = pk(v.x,v.x); UY = pk(v.y,v.y); }
            acc1[i] = f2fma(UX, A1_, acc1[i]);
            acc1[i] = f2fma(UY, W1,  acc1[i]);
        }
        addr += Sp;
    }
    addr = base;
    #pragma unroll
    for (int i=0;i<8;i++){ st0[addr]=upk(acc0[i]); st1[addr]=upk(acc1[i]); addr += Sp; }
}

__device__ __forceinline__ int gate_kind(int s){
    if (s < 4) return s;
    int u = s-4, r = u%10;
    return (r < 6) ? 4+r : (r-6);
}
__device__ __forceinline__ const float2* gate_src(int s, int b0, int b1, int t, int& pn){
    if (s < 4){
        pn = 128;
        int b  = (t < 64) ? b0 : b1;
        int tt = (t < 64) ? t  : t-64;
        return g_Dx2 + (b*4+s)*64 + tt;
    }
    int u = s-4, hl = u/10, r = u%10, l = hl>>1, half = hl&1;
    if (r < 6){ pn = PACK; return g_BS2 + (l*12+half*6+r)*PACK + t; }
    pn = 64;
    return (half ? g_Dp2 : g_Sq2) + (l*4+(r-6))*64 + t;
}

__global__ __launch_bounds__(NT)
void k_sim(float* __restrict__ out){
    extern __shared__ char smem_raw[];
    float2* st0 = (float2*)smem_raw;
    float2* st1 = st0 + SSZ;
    float2* buf = st1 + SSZ;              // 2 stages * PACK
    float*  red = (float*)(buf + 2*PACK); // 16*4

    int t = threadIdx.x;
    int b0 = 2*blockIdx.x, b1 = b0 + 1;
    int qq = t >> 6, g = t & 63;

    for (int i=t;i<SSZ;i+=NT){ st0[i] = make_float2(0.f,0.f); st1[i] = make_float2(0.f,0.f); }
    if (t == 0){ st0[0] = make_float2(1.f,0.f); st1[0] = make_float2(1.f,0.f); }
    {   // stage gate 0 (encoding, per-sample: [0..63]=b0, [64..127]=b1)
        int pn; const float2* src = gate_src(0, b0, b1, t, pn);
        if (t < pn) buf[t] = __ldg(src);
    }
    __syncthreads();

    for (int s=0; s<NGATES; s++){
        float2 pre; int pn = 0;
        if (s+1 < NGATES){
            const float2* src = gate_src(s+1, b0, b1, t, pn);
            if (t < pn) pre = __ldg(src);
        }
        const float2* Ub = buf + (s&1)*PACK;
        int k = gate_kind(s);
        if (k < 4){
            int base = (t>>6)*c_A0[k] + ((t>>3)&7)*c_A1[k] + (t&7)*c_A2[k];
            if (s < 4) apply1p2<true >(st0, st1, Ub, Ub+64, base, c_Sp[k]);
            else       apply1p2<false>(st0, st1, Ub, Ub,    base, c_Sp[k]);
        } else {
            int p = k-4;
            int S1p = c_S1p[p], S2p = c_S2p[p];
            int base = (g>>3)*c_T1p[p] + (g&7)*c_T2p[p];
            switch(qq){
                case 0: bs_bucket2<0>(st0,st1,Ub,base,S1p,S2p); break;
                case 1: bs_bucket2<1>(st0,st1,Ub,base,S1p,S2p); break;
                case 2: bs_bucket2<2>(st0,st1,Ub,base,S1p,S2p); break;
                case 3: bs_bucket2<3>(st0,st1,Ub,base,S1p,S2p); break;
                case 4: bs_bucket2<4>(st0,st1,Ub,base,S1p,S2p); break;
                case 5: bs_bucket2<5>(st0,st1,Ub,base,S1p,S2p); break;
                case 6: bs_bucket2<6>(st0,st1,Ub,base,S1p,S2p); break;
                default: bs_bucket2<7>(st0,st1,Ub,base,S1p,S2p); break;
            }
        }
        if (t < pn) buf[((s+1)&1)*PACK + t] = pre;
        __syncthreads();
    }

    // <n_w> per mode, both samples (final Kerr is pure phase: dropped)
    #pragma unroll
    for (int smp=0; smp<2; smp++){
        const float2* st = smp ? st1 : st0;
        float e0=0.f, e1=0.f, e2=0.f, e3=0.f;
        for (int i=t;i<NSTATE;i+=NT){
            float2 v = st[SWZ(i)];
            float p = v.x*v.x + v.y*v.y;
            e0 += p*(float)(i>>9);
            e1 += p*(float)((i>>6)&7);
            e2 += p*(float)((i>>3)&7);
            e3 += p*(float)(i&7);
        }
        #pragma unroll
        for (int o=16;o;o>>=1){
            e0 += __shfl_xor_sync(0xffffffffu, e0, o);
            e1 += __shfl_xor_sync(0xffffffffu, e1, o);
            e2 += __shfl_xor_sync(0xffffffffu, e2, o);
            e3 += __shfl_xor_sync(0xffffffffu, e3, o);
        }
        int wid = t>>5, lane = t&31;
        if (lane == 0){
            red[wid*4+0]=e0; red[wid*4+1]=e1; red[wid*4+2]=e2; red[wid*4+3]=e3;
        }
        __syncthreads();
        if (t < 4){
            float sm = 0.f;
            #pragma unroll
            for (int w=0;w<16;w++) sm += red[w*4+t];
            out[(b0+smp)*4 + t] = sm;
        }
        __syncthreads();
    }
}

extern "C" void kernel_launch(void* const* d_in, const int* in_sizes, int n_in,
                              void* d_out, int out_size) {
    const float* x    = (const float*)d_in[0];
    const float* th1  = (const float*)d_in[1];
    const float* ph1  = (const float*)d_in[2];
    const float* th2  = (const float*)d_in[3];
    const float* ph2  = (const float*)d_in[4];
    const float* dr   = (const float*)d_in[5];
    const float* dphi = (const float*)d_in[6];
    const float* sr   = (const float*)d_in[7];
    const float* sphi = (const float*)d_in[8];
    const float* kerr = (const float*)d_in[9];
    float* out = (float*)d_out;

    static int smem_set = 0;
    if (!smem_set){
        cudaFuncSetAttribute(k_sim, cudaFuncAttributeMaxDynamicSharedMemorySize, SMEM_BYTES);
        smem_set = 1;
    }
    k_prep<<<67, 256>>>(x, th1, ph1, th2, ph2, dr, dphi, sr, sphi, kerr);
    k_sim<<<BATCH/2, NT, SMEM_BYTES>>>(out);
}